// round 10
// baseline (speedup 1.0000x reference)
#include <cuda_runtime.h>
#include <cuda_bf16.h>
#include <cstdint>

typedef unsigned long long ull;

#define GRAPHK   50
#define DFEAT    256
#define BROWS    2048
#define NTILES   391                 // ceil(50000/128)
#define NPADR    (NTILES * 128)      // 50048
#define SIMW     NPADR
#define KC       32
#define NKC      8                   // 256/32 chunks
#define TILEB    8192                // 128 rows x 32 bf16 x 2B
#define BUFB     (6 * TILEB)         // 3 F splits + 3 A splits = 48KB
#define SMGEMM   (2 * BUFB)          // 96KB -> 2 CTAs/SM

#define NEG_INF (-3.402823466e38f)
#define POS_INF ( 3.402823466e38f)
#define FULLMASK 0xffffffffu

__device__ __nv_bfloat16 g_A0[(size_t)NPADR * DFEAT];
__device__ __nv_bfloat16 g_A1[(size_t)NPADR * DFEAT];
__device__ __nv_bfloat16 g_A2[(size_t)NPADR * DFEAT];
__device__ __nv_bfloat16 g_F0[(size_t)BROWS * DFEAT];
__device__ __nv_bfloat16 g_F1[(size_t)BROWS * DFEAT];
__device__ __nv_bfloat16 g_F2[(size_t)BROWS * DFEAT];
__device__ float         g_sim[(size_t)BROWS * SIMW];

__device__ __forceinline__ uint32_t smem_u32(const void* p) {
    uint32_t a;
    asm("{ .reg .u64 t; cvta.to.shared.u64 t, %1; cvt.u32.u64 %0, t; }" : "=r"(a) : "l"(p));
    return a;
}
__device__ __forceinline__ void cpasync16(uint32_t dst, const void* src) {
    asm volatile("cp.async.cg.shared.global [%0], [%1], 16;" :: "r"(dst), "l"(src));
}
__device__ __forceinline__ void cp_commit() { asm volatile("cp.async.commit_group;" ::: "memory"); }
template <int M> __device__ __forceinline__ void cp_wait() {
    asm volatile("cp.async.wait_group %0;" :: "n"(M) : "memory");
}

#define LDSM4(r, addr) \
    asm volatile("ldmatrix.sync.aligned.m8n8.x4.shared.b16 {%0,%1,%2,%3}, [%4];" \
        : "=r"((r)[0]), "=r"((r)[1]), "=r"((r)[2]), "=r"((r)[3]) : "r"(addr))

#define MMA16816(d, a, b0_, b1_) \
    asm volatile("mma.sync.aligned.m16n8k16.row.col.f32.bf16.bf16.f32 " \
        "{%0,%1,%2,%3}, {%4,%5,%6,%7}, {%8,%9}, {%0,%1,%2,%3};" \
        : "+f"((d)[0]), "+f"((d)[1]), "+f"((d)[2]), "+f"((d)[3]) \
        : "r"((a)[0]), "r"((a)[1]), "r"((a)[2]), "r"((a)[3]), "r"(b0_), "r"(b1_))

// ---- kernel 1: fp32 -> 3-way bf16 split (zero-pad past valid) ----
__global__ void ksplit(const float* __restrict__ src, long valid, long total,
                       __nv_bfloat16* __restrict__ h, __nv_bfloat16* __restrict__ m,
                       __nv_bfloat16* __restrict__ l)
{
    long i  = (long)blockIdx.x * blockDim.x + threadIdx.x;
    long st = (long)gridDim.x * blockDim.x;
    for (; i < total; i += st) {
        float x = (i < valid) ? src[i] : 0.0f;
        __nv_bfloat16 hh = __float2bfloat16(x);
        float r1 = x - __bfloat162float(hh);
        __nv_bfloat16 mm = __float2bfloat16(r1);
        float r2 = r1 - __bfloat162float(mm);
        h[i] = hh; m[i] = mm; l[i] = __float2bfloat16(r2);
    }
}

// ---- kernel 2: HMMA split-GEMM -> g_sim (2 CTAs/SM) ----
__global__ __launch_bounds__(256, 2)
void kgemm()
{
    extern __shared__ char smc[];
    const uint32_t sb = smem_u32(smc);

    const int tx     = threadIdx.x;
    const int lane   = tx & 31;
    const int warp   = tx >> 5;          // 0..7
    const int warp_m = warp & 1;
    const int warp_n = warp >> 1;
    const int mtile  = blockIdx.x & 15;
    const int ntile  = blockIdx.x >> 4;
    const int m0     = mtile * 128;
    const int n0     = ntile * 128;

    const __nv_bfloat16* gF[3] = {g_F0, g_F1, g_F2};
    const __nv_bfloat16* gA[3] = {g_A0, g_A1, g_A2};
    const int pa[6] = {0, 0, 1, 0, 2, 1};
    const int pb[6] = {0, 1, 0, 2, 0, 1};

    const int l7 = lane & 7;
    const int qa = (lane >> 3) & 1;
    const int qb = (lane >> 4) & 1;
    uint32_t rA[4], rB[2];
    #pragma unroll
    for (int mf = 0; mf < 4; mf++) rA[mf] = warp_m * 64 + mf * 16 + qa * 8 + l7;
    #pragma unroll
    for (int ng = 0; ng < 2; ng++) rB[ng] = warp_n * 32 + ng * 16 + qb * 8 + l7;

    // rows are 64B (4 x 16B units); swizzle unit ^= (row>>1)&3
    auto stage = [&](int kc, int buf) {
        const uint32_t base = sb + (uint32_t)buf * BUFB;
        const int kc0 = kc * KC;
        #pragma unroll
        for (int j = 0; j < 12; j++) {
            int gid = tx + 256 * j;       // 0..3071
            int t   = gid >> 9;           // tile 0..5
            int u   = gid & 511;
            int row = u >> 2, ku = u & 3;
            const __nv_bfloat16* sp;
            size_t grow;
            if (t < 3) { sp = gF[t];     grow = (size_t)(m0 + row); }
            else       { sp = gA[t - 3]; grow = (size_t)(n0 + row); }
            const char* src = (const char*)(sp + grow * DFEAT + kc0 + 8 * ku);
            uint32_t dst = base + (uint32_t)(t * TILEB + row * 64 + 16 * (ku ^ ((row >> 1) & 3)));
            cpasync16(dst, src);
        }
        cp_commit();
    };

    float acc[4][4][4];
    #pragma unroll
    for (int i = 0; i < 4; i++)
        #pragma unroll
        for (int j = 0; j < 4; j++)
            #pragma unroll
            for (int c = 0; c < 4; c++) acc[i][j][c] = 0.f;

    stage(0, 0);

    for (int kc = 0; kc < NKC; kc++) {
        const int buf = kc & 1;
        if (kc + 1 < NKC) { stage(kc + 1, buf ^ 1); cp_wait<1>(); }
        else              { cp_wait<0>(); }
        __syncthreads();

        const uint32_t bb = sb + (uint32_t)buf * BUFB;
        #pragma unroll
        for (int p = 0; p < 6; p++) {
            const uint32_t at = bb + pa[p] * TILEB;
            const uint32_t bt = bb + (3 + pb[p]) * TILEB;
            #pragma unroll
            for (int kf = 0; kf < 2; kf++) {
                uint32_t a[4][4], b[2][4];
                #pragma unroll
                for (int mf = 0; mf < 4; mf++)
                    LDSM4(a[mf], at + rA[mf] * 64 + 16 * ((unsigned)((2*kf + qb) ^ ((rA[mf] >> 1) & 3))));
                #pragma unroll
                for (int ng = 0; ng < 2; ng++)
                    LDSM4(b[ng], bt + rB[ng] * 64 + 16 * ((unsigned)((2*kf + qa) ^ ((rB[ng] >> 1) & 3))));
                #pragma unroll
                for (int mf = 0; mf < 4; mf++) {
                    #pragma unroll
                    for (int nf = 0; nf < 4; nf++)
                        MMA16816(acc[mf][nf], a[mf], b[nf >> 1][2 * (nf & 1)], b[nf >> 1][2 * (nf & 1) + 1]);
                }
            }
        }
        __syncthreads();
    }

    const int crow  = lane >> 2;
    const int ccol2 = (lane & 3) * 2;
    #pragma unroll
    for (int mf = 0; mf < 4; mf++) {
        #pragma unroll
        for (int nf = 0; nf < 4; nf++) {
            size_t gr = (size_t)(m0 + warp_m * 64 + mf * 16 + crow);
            size_t gc = (size_t)(n0 + warp_n * 32 + nf * 8 + ccol2);
            float* d = g_sim + gr * SIMW + gc;
            *(float2*)d              = make_float2(acc[mf][nf][0], acc[mf][nf][1]);
            *(float2*)(d + 8 * SIMW) = make_float2(acc[mf][nf][2], acc[mf][nf][3]);
        }
    }
}

// ---- kernel 3: block-per-row top-k (8 warp-partials + exact merge) ----
__global__ __launch_bounds__(256, 2)
void ktopk(const int* __restrict__ labels, const int* __restrict__ anchor_label,
           float* __restrict__ out, int B, int N)
{
    __shared__ float lv[8 * GRAPHK];
    __shared__ int   li[8 * GRAPHK];
    __shared__ float fv[GRAPHK];
    __shared__ int   fi[GRAPHK];

    const int lane = threadIdx.x & 31;
    const int w    = threadIdx.x >> 5;
    const int row  = blockIdx.x;
    if (row >= B) return;

    if (lane < GRAPHK)      { lv[w * GRAPHK + lane]      = NEG_INF; li[w * GRAPHK + lane]      = 0; }
    if (lane + 32 < GRAPHK) { lv[w * GRAPHK + lane + 32] = NEG_INF; li[w * GRAPHK + lane + 32] = 0; }
    __syncwarp();

    // phase 1: warp w scans 128-col blocks w, w+8, w+16, ...
    float mv = NEG_INF; int mp = 0;
    const float* srow = g_sim + (size_t)row * SIMW;
    float* myv = lv + w * GRAPHK;
    int*   myi = li + w * GRAPHK;

    for (int blk = w; blk * 128 < N; blk += 8) {
        const int base = blk * 128;
        float4 v4 = __ldcs((const float4*)(srow + base + lane * 4));
        #pragma unroll
        for (int q = 0; q < 4; q++) {
            int j = base + lane * 4 + q;
            float val = (q == 0) ? v4.x : (q == 1) ? v4.y : (q == 2) ? v4.z : v4.w;
            unsigned mask = __ballot_sync(FULLMASK, (j < N) && (val > mv));
            while (mask) {
                int src = __ffs(mask) - 1; mask &= mask - 1;
                float vv = __shfl_sync(FULLMASK, val, src);
                int   jj = __shfl_sync(FULLMASK, j,   src);
                if (vv > mv) {
                    if (lane == 0) { myv[mp] = vv; myi[mp] = jj; }
                    __syncwarp();
                    float x = (lane < GRAPHK) ? myv[lane] : POS_INF;
                    int   p = lane;
                    if (lane + 32 < GRAPHK) {
                        float x2 = myv[lane + 32];
                        if (x2 < x) { x = x2; p = lane + 32; }
                    }
                    #pragma unroll
                    for (int off = 16; off; off >>= 1) {
                        float ox = __shfl_down_sync(FULLMASK, x, off);
                        int   op = __shfl_down_sync(FULLMASK, p, off);
                        if (ox < x) { x = ox; p = op; }
                    }
                    mv = __shfl_sync(FULLMASK, x, 0);
                    mp = __shfl_sync(FULLMASK, p, 0);
                }
            }
        }
    }
    __syncthreads();

    // phase 2: warp 0 merges 8*50 candidates exactly
    if (w == 0) {
        if (lane < GRAPHK)      { fv[lane]      = NEG_INF; fi[lane]      = 0; }
        if (lane + 32 < GRAPHK) { fv[lane + 32] = NEG_INF; fi[lane + 32] = 0; }
        __syncwarp();
        mv = NEG_INF; mp = 0;

        for (int b = 0; b < (8 * GRAPHK + 31) / 32; b++) {
            int idx = b * 32 + lane;
            bool ok = idx < 8 * GRAPHK;
            float val = ok ? lv[idx] : NEG_INF;
            int   jj0 = ok ? li[idx] : 0;
            unsigned mask = __ballot_sync(FULLMASK, ok && (val > mv));
            while (mask) {
                int src = __ffs(mask) - 1; mask &= mask - 1;
                float vv = __shfl_sync(FULLMASK, val, src);
                int   jj = __shfl_sync(FULLMASK, jj0, src);
                if (vv > mv) {
                    if (lane == 0) { fv[mp] = vv; fi[mp] = jj; }
                    __syncwarp();
                    float x = (lane < GRAPHK) ? fv[lane] : POS_INF;
                    int   p = lane;
                    if (lane + 32 < GRAPHK) {
                        float x2 = fv[lane + 32];
                        if (x2 < x) { x = x2; p = lane + 32; }
                    }
                    #pragma unroll
                    for (int off = 16; off; off >>= 1) {
                        float ox = __shfl_down_sync(FULLMASK, x, off);
                        int   op = __shfl_down_sync(FULLMASK, p, off);
                        if (ox < x) { x = ox; p = op; }
                    }
                    mv = __shfl_sync(FULLMASK, x, 0);
                    mp = __shfl_sync(FULLMASK, p, 0);
                }
            }
        }

        const int lbl = labels[row];
        float sv = 0.f; int cnt = 0;
        if (lane < GRAPHK)      { sv  = fv[lane];      cnt  = (anchor_label[fi[lane]]      == lbl); }
        if (lane + 32 < GRAPHK) { sv += fv[lane + 32]; cnt += (anchor_label[fi[lane + 32]] == lbl); }
        #pragma unroll
        for (int off = 16; off; off >>= 1) {
            sv  += __shfl_down_sync(FULLMASK, sv, off);
            cnt += __shfl_down_sync(FULLMASK, cnt, off);
        }
        if (lane == 0) {
            out[row]     = -(float)cnt * (1.0f / GRAPHK);
            out[B + row] = sv * (1.0f / GRAPHK);
        }
    }
}

extern "C" void kernel_launch(void* const* d_in, const int* in_sizes, int n_in,
                              void* d_out, int out_size)
{
    const float* features     = (const float*)d_in[0];
    const float* anchor       = (const float*)d_in[1];
    const int*   labels       = (const int*)d_in[2];
    // d_in[3] = t_labels (unused)
    const int*   anchor_label = (const int*)d_in[4];
    float* out = (float*)d_out;
    const int B = in_sizes[2];   // 2048
    const int N = in_sizes[4];   // 50000

    __nv_bfloat16 *a0, *a1, *a2, *f0, *f1, *f2;
    cudaGetSymbolAddress((void**)&a0, g_A0);
    cudaGetSymbolAddress((void**)&a1, g_A1);
    cudaGetSymbolAddress((void**)&a2, g_A2);
    cudaGetSymbolAddress((void**)&f0, g_F0);
    cudaGetSymbolAddress((void**)&f1, g_F1);
    cudaGetSymbolAddress((void**)&f2, g_F2);

    ksplit<<<592, 256>>>(anchor,   (long)N * DFEAT, (long)NPADR * DFEAT, a0, a1, a2);
    ksplit<<<148, 256>>>(features, (long)B * DFEAT, (long)B * DFEAT,     f0, f1, f2);

    cudaFuncSetAttribute(kgemm, cudaFuncAttributeMaxDynamicSharedMemorySize, SMGEMM);
    kgemm<<<NTILES * 16, 256, SMGEMM>>>();

    ktopk<<<B, 256>>>(labels, anchor_label, out, B, N);
}

// round 11
// speedup vs baseline: 1.3126x; 1.3126x over previous
#include <cuda_runtime.h>
#include <cuda_bf16.h>
#include <cstdint>

typedef unsigned long long ull;

#define GRAPHK   50
#define DFEAT    256
#define BROWS    2048
#define NTILES   391                 // ceil(50000/128)
#define NPADR    (NTILES * 128)      // 50048
#define SIMW     NPADR
#define KC       32
#define NKC      8                   // 256/32 chunks
#define TILEB    8192                // 128 rows x 32 bf16 x 2B
#define BUFB     (6 * TILEB)         // 3 F splits + 3 A splits = 48KB
#define SMGEMM   (2 * BUFB)          // 96KB -> 2 CTAs/SM

#define NEG_INF (-3.402823466e38f)
#define POS_INF ( 3.402823466e38f)
#define FULLMASK 0xffffffffu

__device__ __nv_bfloat16 g_A0[(size_t)NPADR * DFEAT];
__device__ __nv_bfloat16 g_A1[(size_t)NPADR * DFEAT];
__device__ __nv_bfloat16 g_A2[(size_t)NPADR * DFEAT];
__device__ __nv_bfloat16 g_F0[(size_t)BROWS * DFEAT];
__device__ __nv_bfloat16 g_F1[(size_t)BROWS * DFEAT];
__device__ __nv_bfloat16 g_F2[(size_t)BROWS * DFEAT];
__device__ float         g_sim[(size_t)BROWS * SIMW];

__device__ __forceinline__ uint32_t smem_u32(const void* p) {
    uint32_t a;
    asm("{ .reg .u64 t; cvta.to.shared.u64 t, %1; cvt.u32.u64 %0, t; }" : "=r"(a) : "l"(p));
    return a;
}
__device__ __forceinline__ void cpasync16(uint32_t dst, const void* src) {
    asm volatile("cp.async.cg.shared.global [%0], [%1], 16;" :: "r"(dst), "l"(src));
}
__device__ __forceinline__ void cp_commit() { asm volatile("cp.async.commit_group;" ::: "memory"); }
template <int M> __device__ __forceinline__ void cp_wait() {
    asm volatile("cp.async.wait_group %0;" :: "n"(M) : "memory");
}

#define LDSM4(r, addr) \
    asm volatile("ldmatrix.sync.aligned.m8n8.x4.shared.b16 {%0,%1,%2,%3}, [%4];" \
        : "=r"((r)[0]), "=r"((r)[1]), "=r"((r)[2]), "=r"((r)[3]) : "r"(addr))

#define MMA16816(d, a, b0_, b1_) \
    asm volatile("mma.sync.aligned.m16n8k16.row.col.f32.bf16.bf16.f32 " \
        "{%0,%1,%2,%3}, {%4,%5,%6,%7}, {%8,%9}, {%0,%1,%2,%3};" \
        : "+f"((d)[0]), "+f"((d)[1]), "+f"((d)[2]), "+f"((d)[3]) \
        : "r"((a)[0]), "r"((a)[1]), "r"((a)[2]), "r"((a)[3]), "r"(b0_), "r"(b1_))

// ---- kernel 1: fp32 -> 3-way bf16 split, vectorized ----
__global__ void ksplit(const float* __restrict__ src, long valid, long total,
                       __nv_bfloat16* __restrict__ h, __nv_bfloat16* __restrict__ m,
                       __nv_bfloat16* __restrict__ l)
{
    long i4 = (long)blockIdx.x * blockDim.x + threadIdx.x;
    long st = (long)gridDim.x * blockDim.x;
    long n4 = total >> 2;
    for (; i4 < n4; i4 += st) {
        long i = i4 << 2;
        float4 x = (i + 3 < valid) ? *(const float4*)(src + i)
                                   : make_float4(0.f, 0.f, 0.f, 0.f);
        float xs[4] = {x.x, x.y, x.z, x.w};
        __nv_bfloat16 hv[4], mv[4], lv[4];
        #pragma unroll
        for (int q = 0; q < 4; q++) {
            __nv_bfloat16 hh = __float2bfloat16(xs[q]);
            float r1 = xs[q] - __bfloat162float(hh);
            __nv_bfloat16 mm = __float2bfloat16(r1);
            float r2 = r1 - __bfloat162float(mm);
            hv[q] = hh; mv[q] = mm; lv[q] = __float2bfloat16(r2);
        }
        *(__nv_bfloat162*)(h + i)     = __nv_bfloat162(hv[0], hv[1]);
        *(__nv_bfloat162*)(h + i + 2) = __nv_bfloat162(hv[2], hv[3]);
        *(__nv_bfloat162*)(m + i)     = __nv_bfloat162(mv[0], mv[1]);
        *(__nv_bfloat162*)(m + i + 2) = __nv_bfloat162(mv[2], mv[3]);
        *(__nv_bfloat162*)(l + i)     = __nv_bfloat162(lv[0], lv[1]);
        *(__nv_bfloat162*)(l + i + 2) = __nv_bfloat162(lv[2], lv[3]);
    }
}

// ---- kernel 2: HMMA split-GEMM -> g_sim (A-split fragment reuse) ----
__global__ __launch_bounds__(256, 2)
void kgemm()
{
    extern __shared__ char smc[];
    const uint32_t sb = smem_u32(smc);

    const int tx     = threadIdx.x;
    const int lane   = tx & 31;
    const int warp   = tx >> 5;          // 0..7
    const int warp_m = warp & 1;
    const int warp_n = warp >> 1;
    const int mtile  = blockIdx.x & 15;
    const int ntile  = blockIdx.x >> 4;
    const int m0     = mtile * 128;
    const int n0     = ntile * 128;

    const __nv_bfloat16* gF[3] = {g_F0, g_F1, g_F2};
    const __nv_bfloat16* gA[3] = {g_A0, g_A1, g_A2};

    const int l7 = lane & 7;
    const int qa = (lane >> 3) & 1;
    const int qb = (lane >> 4) & 1;
    uint32_t rA[4], rB[2];
    #pragma unroll
    for (int mf = 0; mf < 4; mf++) rA[mf] = warp_m * 64 + mf * 16 + qa * 8 + l7;
    #pragma unroll
    for (int ng = 0; ng < 2; ng++) rB[ng] = warp_n * 32 + ng * 16 + qb * 8 + l7;

    // rows are 64B (4 x 16B units); swizzle unit ^= (row>>1)&3
    auto stage = [&](int kc, int buf) {
        const uint32_t base = sb + (uint32_t)buf * BUFB;
        const int kc0 = kc * KC;
        #pragma unroll
        for (int j = 0; j < 12; j++) {
            int gid = tx + 256 * j;       // 0..3071
            int t   = gid >> 9;           // tile 0..5
            int u   = gid & 511;
            int row = u >> 2, ku = u & 3;
            const __nv_bfloat16* sp;
            size_t grow;
            if (t < 3) { sp = gF[t];     grow = (size_t)(m0 + row); }
            else       { sp = gA[t - 3]; grow = (size_t)(n0 + row); }
            const char* src = (const char*)(sp + grow * DFEAT + kc0 + 8 * ku);
            uint32_t dst = base + (uint32_t)(t * TILEB + row * 64 + 16 * (ku ^ ((row >> 1) & 3)));
            cpasync16(dst, src);
        }
        cp_commit();
    };

    float acc[4][4][4];
    #pragma unroll
    for (int i = 0; i < 4; i++)
        #pragma unroll
        for (int j = 0; j < 4; j++)
            #pragma unroll
            for (int c = 0; c < 4; c++) acc[i][j][c] = 0.f;

    stage(0, 0);

    for (int kc = 0; kc < NKC; kc++) {
        const int buf = kc & 1;
        if (kc + 1 < NKC) { stage(kc + 1, buf ^ 1); cp_wait<1>(); }
        else              { cp_wait<0>(); }
        __syncthreads();

        const uint32_t bb = sb + (uint32_t)buf * BUFB;
        #pragma unroll
        for (int kf = 0; kf < 2; kf++) {
            // group products by A split: A0*{B0,B1,B2}, A1*{B0,B1}, A2*{B0}
            #pragma unroll
            for (int sa = 0; sa < 3; sa++) {
                uint32_t a[4][4];
                const uint32_t at = bb + sa * TILEB;
                #pragma unroll
                for (int mf = 0; mf < 4; mf++)
                    LDSM4(a[mf], at + rA[mf] * 64 + 16 * ((unsigned)((2*kf + qb) ^ ((rA[mf] >> 1) & 3))));
                #pragma unroll
                for (int sbp = 0; sbp < 3 - sa; sbp++) {
                    uint32_t b[2][4];
                    const uint32_t bt = bb + (3 + sbp) * TILEB;
                    #pragma unroll
                    for (int ng = 0; ng < 2; ng++)
                        LDSM4(b[ng], bt + rB[ng] * 64 + 16 * ((unsigned)((2*kf + qa) ^ ((rB[ng] >> 1) & 3))));
                    #pragma unroll
                    for (int mf = 0; mf < 4; mf++) {
                        #pragma unroll
                        for (int nf = 0; nf < 4; nf++)
                            MMA16816(acc[mf][nf], a[mf], b[nf >> 1][2 * (nf & 1)], b[nf >> 1][2 * (nf & 1) + 1]);
                    }
                }
            }
        }
        __syncthreads();
    }

    const int crow  = lane >> 2;
    const int ccol2 = (lane & 3) * 2;
    #pragma unroll
    for (int mf = 0; mf < 4; mf++) {
        #pragma unroll
        for (int nf = 0; nf < 4; nf++) {
            size_t gr = (size_t)(m0 + warp_m * 64 + mf * 16 + crow);
            size_t gc = (size_t)(n0 + warp_n * 32 + nf * 8 + ccol2);
            float* d = g_sim + gr * SIMW + gc;
            __stcs((float2*)d,              make_float2(acc[mf][nf][0], acc[mf][nf][1]));
            __stcs((float2*)(d + 8 * SIMW), make_float2(acc[mf][nf][2], acc[mf][nf][3]));
        }
    }
}

// ---- kernel 3: warp-per-row top-k with depth-4 prefetch ----
__global__ __launch_bounds__(256, 4)
void ktopk(const int* __restrict__ labels, const int* __restrict__ anchor_label,
           float* __restrict__ out, int B, int N)
{
    __shared__ float vals[8][GRAPHK];
    __shared__ int   inds[8][GRAPHK];
    const int lane = threadIdx.x & 31;
    const int w    = threadIdx.x >> 5;
    const int row  = blockIdx.x * 8 + w;
    if (row >= B) return;

    if (lane < GRAPHK)      { vals[w][lane]      = NEG_INF; inds[w][lane]      = 0; }
    if (lane + 32 < GRAPHK) { vals[w][lane + 32] = NEG_INF; inds[w][lane + 32] = 0; }
    __syncwarp();

    float mv = NEG_INF; int mp = 0;
    const float* srow = g_sim + (size_t)row * SIMW;
    const int NIT = SIMW / 128;              // 391; padded cols masked by j<N

    float4 pf[4];
    #pragma unroll
    for (int d = 0; d < 4; d++)
        pf[d] = __ldcs((const float4*)(srow + d * 128 + lane * 4));

    for (int it = 0; it < NIT; it++) {
        float4 cur = pf[it & 3];
        int nx = it + 4;
        if (nx < NIT)
            pf[it & 3] = __ldcs((const float4*)(srow + nx * 128 + lane * 4));

        const int jb = it * 128 + lane * 4;
        #pragma unroll
        for (int q = 0; q < 4; q++) {
            int j = jb + q;
            float val = (q == 0) ? cur.x : (q == 1) ? cur.y : (q == 2) ? cur.z : cur.w;
            unsigned mask = __ballot_sync(FULLMASK, (j < N) && (val > mv));
            while (mask) {
                int src = __ffs(mask) - 1; mask &= mask - 1;
                float vv = __shfl_sync(FULLMASK, val, src);
                int   jj = __shfl_sync(FULLMASK, j,   src);
                if (vv > mv) {
                    if (lane == 0) { vals[w][mp] = vv; inds[w][mp] = jj; }
                    __syncwarp();
                    float x = (lane < GRAPHK) ? vals[w][lane] : POS_INF;
                    int   p = lane;
                    if (lane + 32 < GRAPHK) {
                        float x2 = vals[w][lane + 32];
                        if (x2 < x) { x = x2; p = lane + 32; }
                    }
                    #pragma unroll
                    for (int off = 16; off; off >>= 1) {
                        float ox = __shfl_down_sync(FULLMASK, x, off);
                        int   op = __shfl_down_sync(FULLMASK, p, off);
                        if (ox < x) { x = ox; p = op; }
                    }
                    mv = __shfl_sync(FULLMASK, x, 0);
                    mp = __shfl_sync(FULLMASK, p, 0);
                }
            }
        }
    }

    const int lbl = labels[row];
    float sv = 0.f; int cnt = 0;
    if (lane < GRAPHK)      { sv  = vals[w][lane];      cnt  = (anchor_label[inds[w][lane]]      == lbl); }
    if (lane + 32 < GRAPHK) { sv += vals[w][lane + 32]; cnt += (anchor_label[inds[w][lane + 32]] == lbl); }
    #pragma unroll
    for (int off = 16; off; off >>= 1) {
        sv  += __shfl_down_sync(FULLMASK, sv, off);
        cnt += __shfl_down_sync(FULLMASK, cnt, off);
    }
    if (lane == 0) {
        out[row]     = -(float)cnt * (1.0f / GRAPHK);
        out[B + row] = sv * (1.0f / GRAPHK);
    }
}

extern "C" void kernel_launch(void* const* d_in, const int* in_sizes, int n_in,
                              void* d_out, int out_size)
{
    const float* features     = (const float*)d_in[0];
    const float* anchor       = (const float*)d_in[1];
    const int*   labels       = (const int*)d_in[2];
    // d_in[3] = t_labels (unused)
    const int*   anchor_label = (const int*)d_in[4];
    float* out = (float*)d_out;
    const int B = in_sizes[2];   // 2048
    const int N = in_sizes[4];   // 50000

    __nv_bfloat16 *a0, *a1, *a2, *f0, *f1, *f2;
    cudaGetSymbolAddress((void**)&a0, g_A0);
    cudaGetSymbolAddress((void**)&a1, g_A1);
    cudaGetSymbolAddress((void**)&a2, g_A2);
    cudaGetSymbolAddress((void**)&f0, g_F0);
    cudaGetSymbolAddress((void**)&f1, g_F1);
    cudaGetSymbolAddress((void**)&f2, g_F2);

    ksplit<<<592, 256>>>(anchor,   (long)N * DFEAT, (long)NPADR * DFEAT, a0, a1, a2);
    ksplit<<<148, 256>>>(features, (long)B * DFEAT, (long)B * DFEAT,     f0, f1, f2);

    cudaFuncSetAttribute(kgemm, cudaFuncAttributeMaxDynamicSharedMemorySize, SMGEMM);
    kgemm<<<NTILES * 16, 256, SMGEMM>>>();

    ktopk<<<(B + 7) / 8, 256>>>(labels, anchor_label, out, B, N);
}